// round 2
// baseline (speedup 1.0000x reference)
#include <cuda_runtime.h>
#include <cuda_bf16.h>
#include <cstdint>

// out[b,t] = sum_d x[b,t,d] * stimulus[b,t,d]
// B=8, T=8192, D=768 (fp32). Pure HBM-streaming kernel.
//
// One warp per row (row = b*T + t). D=768 floats = 192 float4 per input.
// Each lane handles 6 float4 from each input (192/32), strided by 32 lanes,
// giving fully-coalesced 512B/warp LDG.128 transactions and 12 independent
// loads in flight per lane for latency hiding. Warp-shuffle tree reduction,
// lane 0 writes the scalar result.

static constexpr int D = 768;
static constexpr int VEC_PER_ROW = D / 4;        // 192 float4
static constexpr int VEC_PER_LANE = VEC_PER_ROW / 32;  // 6

__global__ void __launch_bounds__(256)
dot_rows_kernel(const float4* __restrict__ x,
                const float4* __restrict__ s,
                float* __restrict__ out,
                int n_rows)
{
    const int warp_in_block = threadIdx.x >> 5;
    const int lane = threadIdx.x & 31;
    const int row = blockIdx.x * (blockDim.x >> 5) + warp_in_block;
    if (row >= n_rows) return;

    const float4* xr = x + (size_t)row * VEC_PER_ROW;
    const float4* sr = s + (size_t)row * VEC_PER_ROW;

    float acc = 0.0f;
#pragma unroll
    for (int i = 0; i < VEC_PER_LANE; ++i) {
        const int idx = lane + i * 32;
        float4 a = xr[idx];
        float4 b = sr[idx];
        acc = fmaf(a.x, b.x, acc);
        acc = fmaf(a.y, b.y, acc);
        acc = fmaf(a.z, b.z, acc);
        acc = fmaf(a.w, b.w, acc);
    }

    // warp tree reduce
#pragma unroll
    for (int off = 16; off > 0; off >>= 1)
        acc += __shfl_xor_sync(0xFFFFFFFFu, acc, off);

    if (lane == 0)
        out[row] = acc;
}

extern "C" void kernel_launch(void* const* d_in, const int* in_sizes, int n_in,
                              void* d_out, int out_size)
{
    const float4* x = (const float4*)d_in[0];
    const float4* s = (const float4*)d_in[1];
    float* out = (float*)d_out;

    const int n_rows = out_size;           // B*T = 65536
    const int warps_per_block = 8;         // 256 threads
    const int blocks = (n_rows + warps_per_block - 1) / warps_per_block;

    dot_rows_kernel<<<blocks, 256>>>(x, s, out, n_rows);
}

// round 3
// speedup vs baseline: 1.0273x; 1.0273x over previous
#include <cuda_runtime.h>
#include <cuda_bf16.h>
#include <cstdint>

// out[b,t] = sum_d x[b,t,d] * stimulus[b,t,d]
// B=8, T=8192, D=768 (fp32). HBM-bound streaming kernel.
//
// One warp per row. Each lane loads its 6 float4 from BOTH streams into
// registers up-front (12 independent LDG.128.CS in flight per lane) before
// any FMA, maximizing MLP and DRAM queue depth. __ldcs = evict-first
// (read-once data). Warp-shuffle reduce, lane 0 stores.

static constexpr int D = 768;
static constexpr int VEC_PER_ROW = D / 4;              // 192 float4
static constexpr int VEC_PER_LANE = VEC_PER_ROW / 32;  // 6

__global__ void __launch_bounds__(256)
dot_rows_kernel(const float4* __restrict__ x,
                const float4* __restrict__ s,
                float* __restrict__ out,
                int n_rows)
{
    const int warp_in_block = threadIdx.x >> 5;
    const int lane = threadIdx.x & 31;
    const int row = blockIdx.x * (blockDim.x >> 5) + warp_in_block;
    if (row >= n_rows) return;

    const float4* xr = x + (size_t)row * VEC_PER_ROW;
    const float4* sr = s + (size_t)row * VEC_PER_ROW;

    // Batch ALL loads first: 12 independent 16B loads in flight per lane.
    float4 a[VEC_PER_LANE];
    float4 b[VEC_PER_LANE];
#pragma unroll
    for (int i = 0; i < VEC_PER_LANE; ++i)
        a[i] = __ldcs(xr + lane + i * 32);
#pragma unroll
    for (int i = 0; i < VEC_PER_LANE; ++i)
        b[i] = __ldcs(sr + lane + i * 32);

    float acc = 0.0f;
#pragma unroll
    for (int i = 0; i < VEC_PER_LANE; ++i) {
        acc = fmaf(a[i].x, b[i].x, acc);
        acc = fmaf(a[i].y, b[i].y, acc);
        acc = fmaf(a[i].z, b[i].z, acc);
        acc = fmaf(a[i].w, b[i].w, acc);
    }

    // warp tree reduce
#pragma unroll
    for (int off = 16; off > 0; off >>= 1)
        acc += __shfl_xor_sync(0xFFFFFFFFu, acc, off);

    if (lane == 0)
        out[row] = acc;
}

extern "C" void kernel_launch(void* const* d_in, const int* in_sizes, int n_in,
                              void* d_out, int out_size)
{
    const float4* x = (const float4*)d_in[0];
    const float4* s = (const float4*)d_in[1];
    float* out = (float*)d_out;

    const int n_rows = out_size;           // B*T = 65536
    const int warps_per_block = 8;         // 256 threads
    const int blocks = (n_rows + warps_per_block - 1) / warps_per_block;

    dot_rows_kernel<<<blocks, 256>>>(x, s, out, n_rows);
}